// round 9
// baseline (speedup 1.0000x reference)
#include <cuda_runtime.h>

// ---------------------------------------------------------------------------
// WeightedMSELoss: loss = sum(w(t) * (p - t)^2) / sum(weights)
// w(t) = weights[i] for edge[i] < t <= edge[i+1]; 0 outside (edge[0], edge[5]].
// Inputs (metadata order): predicted[N] f32, target[N] f32, weights[5] f32, edge[6] f32
// Output: scalar f32.
//
// R5 ncu: DRAM 75.8%, issue 39.6%, occ 93% -> latency-bound, not at BW ceiling.
// (verified: alu=45% == 12 ALU warp-ops/element select chain; not binding)
// Fix: 4x-stride unroll, 8 front-batched LDG.128 per iteration (2x MLP),
// 4 independent accumulators. Fused last-block-done finalize retained.
// ---------------------------------------------------------------------------

#define NBLOCKS  1184      // 148 SMs * 8 CTAs
#define NTHREADS 256

__device__ float        g_partials[NBLOCKS];
__device__ unsigned int g_done_count = 0;   // self-resetting; 0 at every launch start

__device__ __forceinline__ float elem_loss(float p, float t,
                                           float e0, float e1, float e2, float e3,
                                           float e4, float e5,
                                           float w0, float w1, float w2, float w3, float w4) {
    // Straight-line select chain -> FSEL, no branches.
    float w = w4;
    w = (t <= e4) ? w3 : w;
    w = (t <= e3) ? w2 : w;
    w = (t <= e2) ? w1 : w;
    w = (t <= e1) ? w0 : w;
    w = (t <= e0) ? 0.0f : w;
    w = (t >  e5) ? 0.0f : w;
    float d = p - t;
    return w * d * d;
}

#define ACC4(acc, pv, tv) do {                                            \
    acc += elem_loss((pv).x, (tv).x, e0,e1,e2,e3,e4,e5, w0,w1,w2,w3,w4);  \
    acc += elem_loss((pv).y, (tv).y, e0,e1,e2,e3,e4,e5, w0,w1,w2,w3,w4);  \
    acc += elem_loss((pv).z, (tv).z, e0,e1,e2,e3,e4,e5, w0,w1,w2,w3,w4);  \
    acc += elem_loss((pv).w, (tv).w, e0,e1,e2,e3,e4,e5, w0,w1,w2,w3,w4);  \
} while (0)

__global__ void __launch_bounds__(NTHREADS)
wmse_fused_kernel(const float4* __restrict__ pred4,
                  const float4* __restrict__ targ4,
                  const float*  __restrict__ pred,
                  const float*  __restrict__ targ,
                  const float*  __restrict__ weights,
                  const float*  __restrict__ edge,
                  float* __restrict__ out,
                  int n4, int n) {
    // Uniform scalars: read-only path, hoisted before the streaming loop.
    const float e0 = __ldg(&edge[0]), e1 = __ldg(&edge[1]), e2 = __ldg(&edge[2]),
                e3 = __ldg(&edge[3]), e4 = __ldg(&edge[4]), e5 = __ldg(&edge[5]);
    const float w0 = __ldg(&weights[0]), w1 = __ldg(&weights[1]),
                w2 = __ldg(&weights[2]), w3 = __ldg(&weights[3]),
                w4 = __ldg(&weights[4]);

    float acc0 = 0.0f, acc1 = 0.0f, acc2 = 0.0f, acc3 = 0.0f;
    const int tid_global = blockIdx.x * blockDim.x + threadIdx.x;
    const int stride = gridDim.x * blockDim.x;

    // Main loop: 4x float4 per iteration; all 8 LDG.128 issued before any use.
    int i = tid_global;
    for (; i + 3 * stride < n4; i += 4 * stride) {
        float4 pa = pred4[i];
        float4 ta = targ4[i];
        float4 pb = pred4[i + stride];
        float4 tb = targ4[i + stride];
        float4 pc = pred4[i + 2 * stride];
        float4 tc = targ4[i + 2 * stride];
        float4 pd = pred4[i + 3 * stride];
        float4 td = targ4[i + 3 * stride];
        ACC4(acc0, pa, ta);
        ACC4(acc1, pb, tb);
        ACC4(acc2, pc, tc);
        ACC4(acc3, pd, td);
    }
    // Remainder float4s
    for (; i < n4; i += stride) {
        float4 p = pred4[i];
        float4 t = targ4[i];
        ACC4(acc0, p, t);
    }
    // Scalar tail (N not a multiple of 4)
    int tail_idx = n4 * 4 + tid_global;
    if (tail_idx < n) {
        acc0 += elem_loss(pred[tail_idx], targ[tail_idx],
                          e0,e1,e2,e3,e4,e5, w0,w1,w2,w3,w4);
    }

    float acc = (acc0 + acc1) + (acc2 + acc3);

    // Deterministic block tree reduction
    __shared__ float sdata[NTHREADS];
    __shared__ bool  s_is_last;
    int tid = threadIdx.x;
    sdata[tid] = acc;
    __syncthreads();
    #pragma unroll
    for (int s = NTHREADS / 2; s > 32; s >>= 1) {
        if (tid < s) sdata[tid] += sdata[tid + s];
        __syncthreads();
    }
    if (tid < 32) {
        float v = sdata[tid] + sdata[tid + 32];
        #pragma unroll
        for (int off = 16; off > 0; off >>= 1)
            v += __shfl_down_sync(0xFFFFFFFFu, v, off);
        if (tid == 0) g_partials[blockIdx.x] = v;
    }

    // ---- last-block-done fused finalize ----
    if (tid == 0) {
        __threadfence();  // publish g_partials[blockIdx.x] before the ticket
        unsigned int ticket = atomicAdd(&g_done_count, 1u);
        s_is_last = (ticket == (unsigned int)(gridDim.x - 1));
    }
    __syncthreads();

    if (s_is_last) {
        // All other blocks' partials are visible (fence before their tickets).
        float v = 0.0f;
        for (int k = tid; k < NBLOCKS; k += NTHREADS) v += g_partials[k];
        sdata[tid] = v;
        __syncthreads();
        #pragma unroll
        for (int s = NTHREADS / 2; s > 32; s >>= 1) {
            if (tid < s) sdata[tid] += sdata[tid + s];
            __syncthreads();
        }
        if (tid < 32) {
            float x = sdata[tid] + sdata[tid + 32];
            #pragma unroll
            for (int off = 16; off > 0; off >>= 1)
                x += __shfl_down_sync(0xFFFFFFFFu, x, off);
            if (tid == 0) {
                float wsum = w0 + w1 + w2 + w3 + w4;
                out[0] = x / wsum;
                g_done_count = 0;   // reset for next graph replay (deterministic)
            }
        }
    }
}

extern "C" void kernel_launch(void* const* d_in, const int* in_sizes, int n_in,
                              void* d_out, int out_size) {
    const float* pred    = (const float*)d_in[0];
    const float* targ    = (const float*)d_in[1];
    const float* weights = (const float*)d_in[2];
    const float* edge    = (const float*)d_in[3];
    float* out = (float*)d_out;

    int n  = in_sizes[0];
    int n4 = n / 4;

    wmse_fused_kernel<<<NBLOCKS, NTHREADS>>>(
        (const float4*)pred, (const float4*)targ, pred, targ,
        weights, edge, out, n4, n);
}

// round 10
// speedup vs baseline: 1.1706x; 1.1706x over previous
#include <cuda_runtime.h>

// ---------------------------------------------------------------------------
// WeightedMSELoss: loss = sum(w(t) * (p - t)^2) / sum(weights)
// w(t) = weights[i] for edge[i] < t <= edge[i+1]; 0 outside (edge[0], edge[5]].
// Inputs (metadata order): predicted[N] f32, target[N] f32, weights[5] f32, edge[6] f32
// Output: scalar f32.
//
// R9 post-mortem: 4x unroll raised per-warp MLP (DRAM%/warp 1.27->1.72) but
// regs=38 dropped CTAs/SM to 6, and NBLOCKS=1184 became 1.33 waves -> occ 59%,
// DRAM 65%. Fix: single clean wave at 6 CTAs/SM (NBLOCKS=888) + launch_bounds
// pinning 6 blocks/SM. Streaming loop unchanged from R9.
// ---------------------------------------------------------------------------

#define NBLOCKS  888       // 148 SMs * 6 CTAs  (one full wave at 38-42 regs)
#define NTHREADS 256

__device__ float        g_partials[NBLOCKS];
__device__ unsigned int g_done_count = 0;   // self-resetting; 0 at every launch start

__device__ __forceinline__ float elem_loss(float p, float t,
                                           float e0, float e1, float e2, float e3,
                                           float e4, float e5,
                                           float w0, float w1, float w2, float w3, float w4) {
    // Straight-line select chain -> FSEL, no branches.
    float w = w4;
    w = (t <= e4) ? w3 : w;
    w = (t <= e3) ? w2 : w;
    w = (t <= e2) ? w1 : w;
    w = (t <= e1) ? w0 : w;
    w = (t <= e0) ? 0.0f : w;
    w = (t >  e5) ? 0.0f : w;
    float d = p - t;
    return w * d * d;
}

#define ACC4(acc, pv, tv) do {                                            \
    acc += elem_loss((pv).x, (tv).x, e0,e1,e2,e3,e4,e5, w0,w1,w2,w3,w4);  \
    acc += elem_loss((pv).y, (tv).y, e0,e1,e2,e3,e4,e5, w0,w1,w2,w3,w4);  \
    acc += elem_loss((pv).z, (tv).z, e0,e1,e2,e3,e4,e5, w0,w1,w2,w3,w4);  \
    acc += elem_loss((pv).w, (tv).w, e0,e1,e2,e3,e4,e5, w0,w1,w2,w3,w4);  \
} while (0)

__global__ void __launch_bounds__(NTHREADS, 6)
wmse_fused_kernel(const float4* __restrict__ pred4,
                  const float4* __restrict__ targ4,
                  const float*  __restrict__ pred,
                  const float*  __restrict__ targ,
                  const float*  __restrict__ weights,
                  const float*  __restrict__ edge,
                  float* __restrict__ out,
                  int n4, int n) {
    // Uniform scalars: read-only path, hoisted before the streaming loop.
    const float e0 = __ldg(&edge[0]), e1 = __ldg(&edge[1]), e2 = __ldg(&edge[2]),
                e3 = __ldg(&edge[3]), e4 = __ldg(&edge[4]), e5 = __ldg(&edge[5]);
    const float w0 = __ldg(&weights[0]), w1 = __ldg(&weights[1]),
                w2 = __ldg(&weights[2]), w3 = __ldg(&weights[3]),
                w4 = __ldg(&weights[4]);

    float acc0 = 0.0f, acc1 = 0.0f, acc2 = 0.0f, acc3 = 0.0f;
    const int tid_global = blockIdx.x * blockDim.x + threadIdx.x;
    const int stride = gridDim.x * blockDim.x;

    // Main loop: 4x float4 per iteration; all 8 LDG.128 issued before any use.
    int i = tid_global;
    for (; i + 3 * stride < n4; i += 4 * stride) {
        float4 pa = pred4[i];
        float4 ta = targ4[i];
        float4 pb = pred4[i + stride];
        float4 tb = targ4[i + stride];
        float4 pc = pred4[i + 2 * stride];
        float4 tc = targ4[i + 2 * stride];
        float4 pd = pred4[i + 3 * stride];
        float4 td = targ4[i + 3 * stride];
        ACC4(acc0, pa, ta);
        ACC4(acc1, pb, tb);
        ACC4(acc2, pc, tc);
        ACC4(acc3, pd, td);
    }
    // Remainder float4s
    for (; i < n4; i += stride) {
        float4 p = pred4[i];
        float4 t = targ4[i];
        ACC4(acc0, p, t);
    }
    // Scalar tail (N not a multiple of 4)
    int tail_idx = n4 * 4 + tid_global;
    if (tail_idx < n) {
        acc0 += elem_loss(pred[tail_idx], targ[tail_idx],
                          e0,e1,e2,e3,e4,e5, w0,w1,w2,w3,w4);
    }

    float acc = (acc0 + acc1) + (acc2 + acc3);

    // Deterministic block tree reduction
    __shared__ float sdata[NTHREADS];
    __shared__ bool  s_is_last;
    int tid = threadIdx.x;
    sdata[tid] = acc;
    __syncthreads();
    #pragma unroll
    for (int s = NTHREADS / 2; s > 32; s >>= 1) {
        if (tid < s) sdata[tid] += sdata[tid + s];
        __syncthreads();
    }
    if (tid < 32) {
        float v = sdata[tid] + sdata[tid + 32];
        #pragma unroll
        for (int off = 16; off > 0; off >>= 1)
            v += __shfl_down_sync(0xFFFFFFFFu, v, off);
        if (tid == 0) g_partials[blockIdx.x] = v;
    }

    // ---- last-block-done fused finalize ----
    if (tid == 0) {
        __threadfence();  // publish g_partials[blockIdx.x] before the ticket
        unsigned int ticket = atomicAdd(&g_done_count, 1u);
        s_is_last = (ticket == (unsigned int)(gridDim.x - 1));
    }
    __syncthreads();

    if (s_is_last) {
        // All other blocks' partials are visible (fence before their tickets).
        float v = 0.0f;
        for (int k = tid; k < NBLOCKS; k += NTHREADS) v += g_partials[k];
        sdata[tid] = v;
        __syncthreads();
        #pragma unroll
        for (int s = NTHREADS / 2; s > 32; s >>= 1) {
            if (tid < s) sdata[tid] += sdata[tid + s];
            __syncthreads();
        }
        if (tid < 32) {
            float x = sdata[tid] + sdata[tid + 32];
            #pragma unroll
            for (int off = 16; off > 0; off >>= 1)
                x += __shfl_down_sync(0xFFFFFFFFu, x, off);
            if (tid == 0) {
                float wsum = w0 + w1 + w2 + w3 + w4;
                out[0] = x / wsum;
                g_done_count = 0;   // reset for next graph replay (deterministic)
            }
        }
    }
}

extern "C" void kernel_launch(void* const* d_in, const int* in_sizes, int n_in,
                              void* d_out, int out_size) {
    const float* pred    = (const float*)d_in[0];
    const float* targ    = (const float*)d_in[1];
    const float* weights = (const float*)d_in[2];
    const float* edge    = (const float*)d_in[3];
    float* out = (float*)d_out;

    int n  = in_sizes[0];
    int n4 = n / 4;

    wmse_fused_kernel<<<NBLOCKS, NTHREADS>>>(
        (const float4*)pred, (const float4*)targ, pred, targ,
        weights, edge, out, n4, n);
}